// round 1
// baseline (speedup 1.0000x reference)
#include <cuda_runtime.h>
#include <cstdint>

#define NV 4096
#define NE 16384
#define IN_V 128
#define OUT_V 128
#define IN_E 64

// Scratch (device globals: no allocation allowed)
__device__ float g_A[(size_t)NV * NV];       // adjusted adjacency, 64 MB
__device__ float g_diag[NE];                 // per-edge scalars
__device__ float g_X[NV * OUT_V];            // H_v @ weight

__device__ __forceinline__ uint32_t f2tf32(float f) {
    uint32_t u;
    asm("cvt.rna.tf32.f32 %0, %1;" : "=r"(u) : "f"(f));
    return u;
}

// ---------------------------------------------------------------------------
// K1: g_diag[e] = dot(H_e[e,:], p)
// ---------------------------------------------------------------------------
__global__ void k_diag(const float* __restrict__ He, const float* __restrict__ p) {
    __shared__ float sp[IN_E];
    if (threadIdx.x < IN_E) sp[threadIdx.x] = p[threadIdx.x];
    __syncthreads();
    int e = blockIdx.x * blockDim.x + threadIdx.x;
    const float* row = He + (size_t)e * IN_E;
    float acc = 0.f;
#pragma unroll
    for (int k = 0; k < IN_E; k++) acc += row[k] * sp[k];
    g_diag[e] = acc;
}

// ---------------------------------------------------------------------------
// K2: g_X = H_v @ weight   (4096x128 @ 128x128, L2-resident, tiny)
// ---------------------------------------------------------------------------
__global__ void k_hvw(const float* __restrict__ Hv, const float* __restrict__ W) {
    int i = blockIdx.x, j = threadIdx.x;
    const float* hr = Hv + i * IN_V;
    float acc = 0.f;
#pragma unroll 16
    for (int k = 0; k < IN_V; k++) acc += hr[k] * W[k * OUT_V + j];
    g_X[i * OUT_V + j] = acc;
}

// ---------------------------------------------------------------------------
// K3: main GEMM: mult = (T * diag) @ T^T ; epilogue: mask diag->1, * adj_v
//     tf32 mma.sync, 128x128x16 block tiles, 8 warps (warp tile 32x64),
//     double-buffered smem, 8-row supertile swizzle for L2 reuse.
// ---------------------------------------------------------------------------
constexpr int BM = 128, BN = 128, BK = 16;
constexpr int LDA = BK + 4;  // stride 20 floats: conflict-free frag LDS

__global__ void __launch_bounds__(256) k_gemm1(const float* __restrict__ T,
                                               const float* __restrict__ adj) {
    __shared__ float As[2][BM][LDA];
    __shared__ float Bs[2][BN][LDA];

    // Block swizzle: supertiles of 8 rows x 32 cols -> A panels stay L2-resident
    const int bid = blockIdx.x;
    constexpr int RSW = 8;
    constexpr int CT = NV / BN;  // 32
    const int rg  = bid / (RSW * CT);
    const int loc = bid % (RSW * CT);
    const int bm = (rg * RSW + (loc % RSW)) * BM;
    const int bn = (loc / RSW) * BN;

    const int tid  = threadIdx.x;
    const int lane = tid & 31;
    const int warp = tid >> 5;
    const int wm = warp & 3;   // 4 warps along M
    const int wn = warp >> 2;  // 2 warps along N
    const int fr = lane >> 2;
    const int fc = lane & 3;

    float acc[2][8][4];
#pragma unroll
    for (int i = 0; i < 2; i++)
#pragma unroll
        for (int j = 0; j < 8; j++)
#pragma unroll
            for (int k = 0; k < 4; k++) acc[i][j][k] = 0.f;

    // Global load mapping: 256 threads cover rows 0..63 (x float4), and +64.
    const int lrow = tid >> 2;        // 0..63
    const int lcol = (tid & 3) * 4;   // 0,4,8,12
    const float* Ag = T + (size_t)(bm + lrow) * NE + lcol;
    const float* Bg = T + (size_t)(bn + lrow) * NE + lcol;

    float4 ar0, ar1, br0, br1;

    auto LDG = [&](int k0) {
        float4 dv = *(const float4*)&g_diag[k0 + lcol];
        ar0 = *(const float4*)(Ag + k0);
        ar1 = *(const float4*)(Ag + (size_t)64 * NE + k0);
        br0 = *(const float4*)(Bg + k0);
        br1 = *(const float4*)(Bg + (size_t)64 * NE + k0);
        ar0.x *= dv.x; ar0.y *= dv.y; ar0.z *= dv.z; ar0.w *= dv.w;
        ar1.x *= dv.x; ar1.y *= dv.y; ar1.z *= dv.z; ar1.w *= dv.w;
    };

    auto STS = [&](int buf) {
        float4 t;
        t.x = __uint_as_float(f2tf32(ar0.x)); t.y = __uint_as_float(f2tf32(ar0.y));
        t.z = __uint_as_float(f2tf32(ar0.z)); t.w = __uint_as_float(f2tf32(ar0.w));
        *(float4*)&As[buf][lrow][lcol] = t;
        t.x = __uint_as_float(f2tf32(ar1.x)); t.y = __uint_as_float(f2tf32(ar1.y));
        t.z = __uint_as_float(f2tf32(ar1.z)); t.w = __uint_as_float(f2tf32(ar1.w));
        *(float4*)&As[buf][lrow + 64][lcol] = t;
        t.x = __uint_as_float(f2tf32(br0.x)); t.y = __uint_as_float(f2tf32(br0.y));
        t.z = __uint_as_float(f2tf32(br0.z)); t.w = __uint_as_float(f2tf32(br0.w));
        *(float4*)&Bs[buf][lrow][lcol] = t;
        t.x = __uint_as_float(f2tf32(br1.x)); t.y = __uint_as_float(f2tf32(br1.y));
        t.z = __uint_as_float(f2tf32(br1.z)); t.w = __uint_as_float(f2tf32(br1.w));
        *(float4*)&Bs[buf][lrow + 64][lcol] = t;
    };

    auto COMPUTE = [&](int buf) {
#pragma unroll
        for (int ks = 0; ks < BK; ks += 8) {
            uint32_t af[2][4];
#pragma unroll
            for (int mt = 0; mt < 2; mt++) {
                int rb = wm * 32 + mt * 16;
                af[mt][0] = __float_as_uint(As[buf][rb + fr][ks + fc]);
                af[mt][1] = __float_as_uint(As[buf][rb + fr + 8][ks + fc]);
                af[mt][2] = __float_as_uint(As[buf][rb + fr][ks + fc + 4]);
                af[mt][3] = __float_as_uint(As[buf][rb + fr + 8][ks + fc + 4]);
            }
            uint32_t bf[8][2];
#pragma unroll
            for (int nt = 0; nt < 8; nt++) {
                int cb = wn * 64 + nt * 8;
                bf[nt][0] = __float_as_uint(Bs[buf][cb + fr][ks + fc]);
                bf[nt][1] = __float_as_uint(Bs[buf][cb + fr][ks + fc + 4]);
            }
#pragma unroll
            for (int mt = 0; mt < 2; mt++)
#pragma unroll
                for (int nt = 0; nt < 8; nt++) {
                    asm volatile(
                        "mma.sync.aligned.m16n8k8.row.col.f32.tf32.tf32.f32 "
                        "{%0,%1,%2,%3}, {%4,%5,%6,%7}, {%8,%9}, {%0,%1,%2,%3};\n"
                        : "+f"(acc[mt][nt][0]), "+f"(acc[mt][nt][1]),
                          "+f"(acc[mt][nt][2]), "+f"(acc[mt][nt][3])
                        : "r"(af[mt][0]), "r"(af[mt][1]), "r"(af[mt][2]), "r"(af[mt][3]),
                          "r"(bf[nt][0]), "r"(bf[nt][1]));
                }
        }
    };

    LDG(0);
    STS(0);
    __syncthreads();
    const int NK = NE / BK;  // 1024
    for (int kc = 0; kc < NK; kc++) {
        int cur = kc & 1;
        if (kc + 1 < NK) LDG((kc + 1) * BK);
        COMPUTE(cur);
        __syncthreads();
        if (kc + 1 < NK) {
            STS(cur ^ 1);
            __syncthreads();
        }
    }

    // Epilogue: A[i][j] = (i==j ? 1 : mult[i][j]) * adj_v[i][j]
#pragma unroll
    for (int mt = 0; mt < 2; mt++) {
#pragma unroll
        for (int nt = 0; nt < 8; nt++) {
            int gi0 = bm + wm * 32 + mt * 16 + fr;
            int gi1 = gi0 + 8;
            int gj  = bn + wn * 64 + nt * 8 + fc * 2;
            float2 ad0 = *(const float2*)&adj[(size_t)gi0 * NV + gj];
            float2 ad1 = *(const float2*)&adj[(size_t)gi1 * NV + gj];
            float v00 = (gi0 == gj)     ? 1.f : acc[mt][nt][0];
            float v01 = (gi0 == gj + 1) ? 1.f : acc[mt][nt][1];
            float v10 = (gi1 == gj)     ? 1.f : acc[mt][nt][2];
            float v11 = (gi1 == gj + 1) ? 1.f : acc[mt][nt][3];
            float2 o0 = make_float2(v00 * ad0.x, v01 * ad0.y);
            float2 o1 = make_float2(v10 * ad1.x, v11 * ad1.y);
            *(float2*)&g_A[(size_t)gi0 * NV + gj] = o0;
            *(float2*)&g_A[(size_t)gi1 * NV + gj] = o1;
        }
    }
}

// ---------------------------------------------------------------------------
// K4a: ret = bias (broadcast init; K4b accumulates atomically on top)
// ---------------------------------------------------------------------------
__global__ void k_bias(float* __restrict__ ret, const float* __restrict__ bias) {
    int idx = blockIdx.x * blockDim.x + threadIdx.x;
    ret[idx] = bias[idx & (OUT_V - 1)];
}

// ---------------------------------------------------------------------------
// K4b: ret += g_A @ g_X   (4096x4096 @ 4096x128), split-K=4, REDG atomics
// ---------------------------------------------------------------------------
constexpr int BM2 = 32, KT2 = 32, NSPLIT = 4;

__global__ void __launch_bounds__(256) k_gemm2(float* __restrict__ ret) {
    __shared__ float As2[BM2][KT2 + 1];
    __shared__ float Xs[KT2][OUT_V];
    const int bm  = blockIdx.x * BM2;
    const int kc0 = blockIdx.y * (NV / NSPLIT);
    const int kc1 = kc0 + NV / NSPLIT;
    const int tid = threadIdx.x;
    const int tx = tid & 31;   // col group: cols tx*4 .. tx*4+3
    const int ty = tid >> 5;   // row group: rows ty*4 .. ty*4+3

    float acc[4][4];
#pragma unroll
    for (int i = 0; i < 4; i++)
#pragma unroll
        for (int j = 0; j < 4; j++) acc[i][j] = 0.f;

    for (int kt = kc0; kt < kc1; kt += KT2) {
        {
            int r = tid >> 3, c4 = (tid & 7) * 4;
            float4 v = *(const float4*)&g_A[(size_t)(bm + r) * NV + kt + c4];
            As2[r][c4] = v.x; As2[r][c4 + 1] = v.y;
            As2[r][c4 + 2] = v.z; As2[r][c4 + 3] = v.w;
        }
#pragma unroll
        for (int i = 0; i < 4; i++) {
            int f = tid + i * 256;
            int r = f >> 5, c4 = (f & 31) * 4;
            *(float4*)&Xs[r][c4] = *(const float4*)&g_X[(kt + r) * OUT_V + c4];
        }
        __syncthreads();
#pragma unroll 8
        for (int k = 0; k < KT2; k++) {
            float a0 = As2[ty * 4 + 0][k];
            float a1 = As2[ty * 4 + 1][k];
            float a2 = As2[ty * 4 + 2][k];
            float a3 = As2[ty * 4 + 3][k];
            float4 b = *(const float4*)&Xs[k][tx * 4];
            acc[0][0] += a0 * b.x; acc[0][1] += a0 * b.y; acc[0][2] += a0 * b.z; acc[0][3] += a0 * b.w;
            acc[1][0] += a1 * b.x; acc[1][1] += a1 * b.y; acc[1][2] += a1 * b.z; acc[1][3] += a1 * b.w;
            acc[2][0] += a2 * b.x; acc[2][1] += a2 * b.y; acc[2][2] += a2 * b.z; acc[2][3] += a2 * b.w;
            acc[3][0] += a3 * b.x; acc[3][1] += a3 * b.y; acc[3][2] += a3 * b.z; acc[3][3] += a3 * b.w;
        }
        __syncthreads();
    }
#pragma unroll
    for (int i = 0; i < 4; i++)
#pragma unroll
        for (int j = 0; j < 4; j++)
            atomicAdd(&ret[(bm + ty * 4 + i) * OUT_V + tx * 4 + j], acc[i][j]);
}

// ---------------------------------------------------------------------------
extern "C" void kernel_launch(void* const* d_in, const int* in_sizes, int n_in,
                              void* d_out, int out_size) {
    const float* Hv   = (const float*)d_in[0];
    const float* He   = (const float*)d_in[1];
    // d_in[2] = adj_e (unused)
    const float* adjv = (const float*)d_in[3];
    const float* T    = (const float*)d_in[4];
    const float* W    = (const float*)d_in[5];
    const float* p    = (const float*)d_in[6];
    const float* bias = (const float*)d_in[7];
    float* out = (float*)d_out;

    k_diag<<<NE / 256, 256>>>(He, p);
    k_hvw<<<NV, OUT_V>>>(Hv, W);
    k_gemm1<<<(NV / BM) * (NV / BN), 256>>>(T, adjv);
    k_bias<<<NV * OUT_V / 256, 256>>>(out, bias);
    k_gemm2<<<dim3(NV / BM2, NSPLIT), 256>>>(out);

    if (out_size >= NV * OUT_V + NE * IN_E) {
        cudaMemcpyAsync(out + NV * OUT_V, He,
                        (size_t)NE * IN_E * sizeof(float),
                        cudaMemcpyDeviceToDevice, 0);
    }
}

// round 4
// speedup vs baseline: 1.8467x; 1.8467x over previous
#include <cuda_runtime.h>
#include <cstdint>

#define NV 4096
#define NE 16384
#define IN_V 128
#define OUT_V 128
#define IN_E 64

// ---------------- device global scratch (no allocation allowed) -------------
__device__ float g_A[(size_t)NV * NV];            // adjusted adjacency, 64 MB
__device__ float g_Td[(size_t)NV * NE];           // rna_tf32(T * diag), 256 MB
__device__ float g_Tt[(size_t)NV * NE];           // rna_tf32(T), 256 MB
__device__ float g_diag[NE];
__device__ float g_X[NV * OUT_V];

__device__ __forceinline__ uint32_t f2tf32(float f) {
    uint32_t u; asm("cvt.rna.tf32.f32 %0, %1;" : "=r"(u) : "f"(f)); return u;
}
__device__ __forceinline__ uint32_t s2u(const void* p) {
    uint32_t a;
    asm("{ .reg .u64 t; cvta.to.shared.u64 t, %1; cvt.u32.u64 %0, t; }" : "=r"(a) : "l"(p));
    return a;
}
__device__ __forceinline__ void cp16(uint32_t dst, const void* src) {
    asm volatile("cp.async.cg.shared.global [%0], [%1], 16;" :: "r"(dst), "l"(src) : "memory");
}

// ---------------------------------------------------------------------------
// K1: g_diag[e] = dot(H_e[e,:], p)
// ---------------------------------------------------------------------------
__global__ void k_diag(const float* __restrict__ He, const float* __restrict__ p) {
    __shared__ float sp[IN_E];
    if (threadIdx.x < IN_E) sp[threadIdx.x] = p[threadIdx.x];
    __syncthreads();
    int e = blockIdx.x * blockDim.x + threadIdx.x;
    const float* row = He + (size_t)e * IN_E;
    float acc = 0.f;
#pragma unroll
    for (int k = 0; k < IN_E; k++) acc += row[k] * sp[k];
    g_diag[e] = acc;
}

// ---------------------------------------------------------------------------
// K1b: g_Td = rna_tf32(T*diag), g_Tt = rna_tf32(T)
// ---------------------------------------------------------------------------
__global__ void __launch_bounds__(256) k_prep(const float* __restrict__ T) {
    size_t i4 = ((size_t)blockIdx.x * 256 + threadIdx.x) * 4;
    int e = (int)(i4 & (NE - 1));
    float4 t = *(const float4*)(T + i4);
    float4 d = *(const float4*)(g_diag + e);
    float4 td, tt;
    td.x = __uint_as_float(f2tf32(t.x * d.x)); td.y = __uint_as_float(f2tf32(t.y * d.y));
    td.z = __uint_as_float(f2tf32(t.z * d.z)); td.w = __uint_as_float(f2tf32(t.w * d.w));
    tt.x = __uint_as_float(f2tf32(t.x)); tt.y = __uint_as_float(f2tf32(t.y));
    tt.z = __uint_as_float(f2tf32(t.z)); tt.w = __uint_as_float(f2tf32(t.w));
    *(float4*)(g_Td + i4) = td;
    *(float4*)(g_Tt + i4) = tt;
}

// ---------------------------------------------------------------------------
// K2: g_X = H_v @ weight
// ---------------------------------------------------------------------------
__global__ void k_hvw(const float* __restrict__ Hv, const float* __restrict__ W) {
    int i = blockIdx.x, j = threadIdx.x;
    const float* hr = Hv + i * IN_V;
    float acc = 0.f;
#pragma unroll 16
    for (int k = 0; k < IN_V; k++) acc += hr[k] * W[k * OUT_V + j];
    g_X[i * OUT_V + j] = acc;
}

// ---------------------------------------------------------------------------
// K3: symmetric tf32 GEMM via mma.sync, upper-triangle tiles only.
//     D = Td @ Tt^T over 128x128 tiles; epilogue writes tile + transpose.
//     4-stage cp.async pipeline, 8 warps, warp tile 32x64.
// ---------------------------------------------------------------------------
constexpr int BM = 128, BK = 16;
constexpr int LDA = 20;                    // floats; 80B rows keep 16B alignment
constexpr int STAGE_B = 2 * BM * LDA * 4;  // 20480 bytes (A half + B half)
constexpr int NSTG = 4;
constexpr int SMEM_G1 = NSTG * STAGE_B;    // 81920
constexpr int NT1 = NV / BM;               // 32
constexpr int NPAIR = NT1 * (NT1 + 1) / 2; // 528
constexpr int NK = NE / BK;                // 1024
constexpr int STR = 129;                   // epilogue staging stride

__global__ void __launch_bounds__(256, 1) k_gemm1(const float* __restrict__ adj) {
    extern __shared__ char smem[];
    const uint32_t sbase = s2u(smem);

    // triangular decode: pid -> (ti, tj), ti <= tj
    int ti = 0, rem = blockIdx.x;
    while (rem >= NT1 - ti) { rem -= NT1 - ti; ti++; }
    const int tj = ti + rem;
    const int bm = ti * BM, bn = tj * BM;

    const int tid  = threadIdx.x;
    const int lane = tid & 31;
    const int warp = tid >> 5;
    const int wm = warp & 3;
    const int wn = warp >> 2;
    const int fr = lane >> 2;
    const int fc = lane & 3;

    float acc[2][8][4];
#pragma unroll
    for (int i = 0; i < 2; i++)
#pragma unroll
        for (int j = 0; j < 8; j++)
#pragma unroll
            for (int k = 0; k < 4; k++) acc[i][j][k] = 0.f;

    // cp.async mapping: 256 threads; row = tid>>2 (0..63, +64), chunk = tid&3
    const int lrow = tid >> 2;
    const int lch  = tid & 3;
    const float* gA = g_Td + (size_t)(bm + lrow) * NE + lch * 4;
    const float* gB = g_Tt + (size_t)(bn + lrow) * NE + lch * 4;
    const uint32_t soA = (uint32_t)(lrow * LDA + lch * 4) * 4;
    const uint32_t soA2 = soA + (uint32_t)(64 * LDA) * 4;

    auto ISSUE = [&](int kc) {
        const int s = kc & (NSTG - 1);
        const uint32_t base = sbase + s * STAGE_B;
        const uint32_t baseB = base + BM * LDA * 4;
        const size_t k0 = (size_t)kc * BK;
        cp16(base + soA,  gA + k0);
        cp16(base + soA2, gA + (size_t)64 * NE + k0);
        cp16(baseB + soA,  gB + k0);
        cp16(baseB + soA2, gB + (size_t)64 * NE + k0);
        asm volatile("cp.async.commit_group;" ::: "memory");
    };

    auto COMPUTE = [&](int kc) {
        const int s = kc & (NSTG - 1);
        const float* As = (const float*)(smem + s * STAGE_B);
        const float* Bs = As + BM * LDA;
#pragma unroll
        for (int ks = 0; ks < BK; ks += 8) {
            uint32_t af[2][4];
#pragma unroll
            for (int mt = 0; mt < 2; mt++) {
                int rb = wm * 32 + mt * 16;
                af[mt][0] = __float_as_uint(As[(rb + fr) * LDA + ks + fc]);
                af[mt][1] = __float_as_uint(As[(rb + fr + 8) * LDA + ks + fc]);
                af[mt][2] = __float_as_uint(As[(rb + fr) * LDA + ks + fc + 4]);
                af[mt][3] = __float_as_uint(As[(rb + fr + 8) * LDA + ks + fc + 4]);
            }
            uint32_t bf[8][2];
#pragma unroll
            for (int nt = 0; nt < 8; nt++) {
                int cb = wn * 64 + nt * 8;
                bf[nt][0] = __float_as_uint(Bs[(cb + fr) * LDA + ks + fc]);
                bf[nt][1] = __float_as_uint(Bs[(cb + fr) * LDA + ks + fc + 4]);
            }
#pragma unroll
            for (int mt = 0; mt < 2; mt++)
#pragma unroll
                for (int nt = 0; nt < 8; nt++) {
                    asm volatile(
                        "mma.sync.aligned.m16n8k8.row.col.f32.tf32.tf32.f32 "
                        "{%0,%1,%2,%3}, {%4,%5,%6,%7}, {%8,%9}, {%0,%1,%2,%3};\n"
                        : "+f"(acc[mt][nt][0]), "+f"(acc[mt][nt][1]),
                          "+f"(acc[mt][nt][2]), "+f"(acc[mt][nt][3])
                        : "r"(af[mt][0]), "r"(af[mt][1]), "r"(af[mt][2]), "r"(af[mt][3]),
                          "r"(bf[nt][0]), "r"(bf[nt][1]));
                }
        }
    };

    ISSUE(0); ISSUE(1); ISSUE(2);
    for (int kc = 0; kc < NK; kc++) {
        asm volatile("cp.async.wait_group 2;" ::: "memory");
        __syncthreads();
        if (kc + 3 < NK) ISSUE(kc + 3);
        COMPUTE(kc);
        __syncthreads();
    }

    // ---------------- epilogue: stage tile, write direct + transposed -------
    float* stg = (float*)smem;
#pragma unroll
    for (int mt = 0; mt < 2; mt++)
#pragma unroll
        for (int nt = 0; nt < 8; nt++) {
            int il0 = wm * 32 + mt * 16 + fr;
            int il1 = il0 + 8;
            int jl  = wn * 64 + nt * 8 + fc * 2;
            stg[il0 * STR + jl]     = acc[mt][nt][0];
            stg[il0 * STR + jl + 1] = acc[mt][nt][1];
            stg[il1 * STR + jl]     = acc[mt][nt][2];
            stg[il1 * STR + jl + 1] = acc[mt][nt][3];
        }
    __syncthreads();

    // direct block: A[bm+r][bn+c]
#pragma unroll 8
    for (int e = 0; e < 64; e++) {
        int idx = tid + e * 256;
        int r = idx >> 7, c = idx & 127;
        int gi = bm + r, gj = bn + c;
        float v = stg[r * STR + c];
        if (gi == gj) v = 1.f;
        g_A[(size_t)gi * NV + gj] = v * adj[(size_t)gi * NV + gj];
    }
    // transposed block: A[bn+r][bm+c]  (off-diagonal tiles only)
    if (ti != tj) {
#pragma unroll 8
        for (int e = 0; e < 64; e++) {
            int idx = tid + e * 256;
            int r = idx >> 7, c = idx & 127;
            int gi = bn + r, gj = bm + c;
            float v = stg[c * STR + r];
            g_A[(size_t)gi * NV + gj] = v * adj[(size_t)gi * NV + gj];
        }
    }
}

// ---------------------------------------------------------------------------
// K4a: ret = bias
// ---------------------------------------------------------------------------
__global__ void k_bias(float* __restrict__ ret, const float* __restrict__ bias) {
    int idx = blockIdx.x * blockDim.x + threadIdx.x;
    ret[idx] = bias[idx & (OUT_V - 1)];
}

// ---------------------------------------------------------------------------
// K4b: ret += g_A @ g_X   (split-K=4, atomics)
// ---------------------------------------------------------------------------
constexpr int BM2 = 32, KT2 = 32, NSPLIT = 4;

__global__ void __launch_bounds__(256) k_gemm2(float* __restrict__ ret) {
    __shared__ float As2[BM2][KT2 + 1];
    __shared__ float Xs[KT2][OUT_V];
    const int bm  = blockIdx.x * BM2;
    const int kc0 = blockIdx.y * (NV / NSPLIT);
    const int kc1 = kc0 + NV / NSPLIT;
    const int tid = threadIdx.x;
    const int tx = tid & 31;
    const int ty = tid >> 5;

    float acc[4][4];
#pragma unroll
    for (int i = 0; i < 4; i++)
#pragma unroll
        for (int j = 0; j < 4; j++) acc[i][j] = 0.f;

    for (int kt = kc0; kt < kc1; kt += KT2) {
        {
            int r = tid >> 3, c4 = (tid & 7) * 4;
            float4 v = *(const float4*)&g_A[(size_t)(bm + r) * NV + kt + c4];
            As2[r][c4] = v.x; As2[r][c4 + 1] = v.y;
            As2[r][c4 + 2] = v.z; As2[r][c4 + 3] = v.w;
        }
#pragma unroll
        for (int i = 0; i < 4; i++) {
            int f = tid + i * 256;
            int r = f >> 5, c4 = (f & 31) * 4;
            *(float4*)&Xs[r][c4] = *(const float4*)&g_X[(kt + r) * OUT_V + c4];
        }
        __syncthreads();
#pragma unroll 8
        for (int k = 0; k < KT2; k++) {
            float a0 = As2[ty * 4 + 0][k];
            float a1 = As2[ty * 4 + 1][k];
            float a2 = As2[ty * 4 + 2][k];
            float a3 = As2[ty * 4 + 3][k];
            float4 b = *(const float4*)&Xs[k][tx * 4];
            acc[0][0] += a0 * b.x; acc[0][1] += a0 * b.y; acc[0][2] += a0 * b.z; acc[0][3] += a0 * b.w;
            acc[1][0] += a1 * b.x; acc[1][1] += a1 * b.y; acc[1][2] += a1 * b.z; acc[1][3] += a1 * b.w;
            acc[2][0] += a2 * b.x; acc[2][1] += a2 * b.y; acc[2][2] += a2 * b.z; acc[2][3] += a2 * b.w;
            acc[3][0] += a3 * b.x; acc[3][1] += a3 * b.y; acc[3][2] += a3 * b.z; acc[3][3] += a3 * b.w;
        }
        __syncthreads();
    }
#pragma unroll
    for (int i = 0; i < 4; i++)
#pragma unroll
        for (int j = 0; j < 4; j++)
            atomicAdd(&ret[(bm + ty * 4 + i) * OUT_V + tx * 4 + j], acc[i][j]);
}

// ---------------------------------------------------------------------------
extern "C" void kernel_launch(void* const* d_in, const int* in_sizes, int n_in,
                              void* d_out, int out_size) {
    const float* Hv   = (const float*)d_in[0];
    const float* He   = (const float*)d_in[1];
    const float* adjv = (const float*)d_in[3];
    const float* T    = (const float*)d_in[4];
    const float* W    = (const float*)d_in[5];
    const float* p    = (const float*)d_in[6];
    const float* bias = (const float*)d_in[7];
    float* out = (float*)d_out;

    static bool cfg = false;
    if (!cfg) {
        cudaFuncSetAttribute(k_gemm1, cudaFuncAttributeMaxDynamicSharedMemorySize, SMEM_G1);
        cfg = true;
    }

    k_diag<<<NE / 256, 256>>>(He, p);
    k_prep<<<(int)(((size_t)NV * NE) / 1024), 256>>>(T);
    k_hvw<<<NV, OUT_V>>>(Hv, W);
    k_gemm1<<<NPAIR, 256, SMEM_G1>>>(adjv);
    k_bias<<<NV * OUT_V / 256, 256>>>(out, bias);
    k_gemm2<<<dim3(NV / BM2, NSPLIT), 256>>>(out);

    if (out_size >= NV * OUT_V + NE * IN_E) {
        cudaMemcpyAsync(out + NV * OUT_V, He,
                        (size_t)NE * IN_E * sizeof(float),
                        cudaMemcpyDeviceToDevice, 0);
    }
}

// round 5
// speedup vs baseline: 2.2092x; 1.1963x over previous
#include <cuda_runtime.h>
#include <cstdint>

#define NV 4096
#define NE 16384
#define IN_V 128
#define OUT_V 128
#define IN_E 64

// ---------------- device global scratch (no allocation allowed) -------------
__device__ float g_A[(size_t)NV * NV];            // adjusted adjacency, 64 MB
__device__ float g_Td[(size_t)NV * NE];           // rna_tf32(T * diag), 256 MB
__device__ float g_Tt[(size_t)NV * NE];           // rna_tf32(T), 256 MB
__device__ float g_diag[NE];
__device__ float g_X[NV * OUT_V];

__device__ __forceinline__ uint32_t f2tf32(float f) {
    uint32_t u; asm("cvt.rna.tf32.f32 %0, %1;" : "=r"(u) : "f"(f)); return u;
}
__device__ __forceinline__ uint32_t s2u(const void* p) {
    uint32_t a;
    asm("{ .reg .u64 t; cvta.to.shared.u64 t, %1; cvt.u32.u64 %0, t; }" : "=r"(a) : "l"(p));
    return a;
}
__device__ __forceinline__ void cp16(uint32_t dst, const void* src) {
    asm volatile("cp.async.cg.shared.global [%0], [%1], 16;" :: "r"(dst), "l"(src) : "memory");
}

// ---------------------------------------------------------------------------
// K1: g_diag[e] = dot(H_e[e,:], p)
// ---------------------------------------------------------------------------
__global__ void k_diag(const float* __restrict__ He, const float* __restrict__ p) {
    __shared__ float sp[IN_E];
    if (threadIdx.x < IN_E) sp[threadIdx.x] = p[threadIdx.x];
    __syncthreads();
    int e = blockIdx.x * blockDim.x + threadIdx.x;
    const float* row = He + (size_t)e * IN_E;
    float acc = 0.f;
#pragma unroll
    for (int k = 0; k < IN_E; k++) acc += row[k] * sp[k];
    g_diag[e] = acc;
}

// ---------------------------------------------------------------------------
// K1b: g_Td = rna_tf32(T*diag), g_Tt = rna_tf32(T)
// ---------------------------------------------------------------------------
__global__ void __launch_bounds__(256) k_prep(const float* __restrict__ T) {
    size_t i4 = ((size_t)blockIdx.x * 256 + threadIdx.x) * 4;
    int e = (int)(i4 & (NE - 1));
    float4 t = *(const float4*)(T + i4);
    float4 d = *(const float4*)(g_diag + e);
    float4 td, tt;
    td.x = __uint_as_float(f2tf32(t.x * d.x)); td.y = __uint_as_float(f2tf32(t.y * d.y));
    td.z = __uint_as_float(f2tf32(t.z * d.z)); td.w = __uint_as_float(f2tf32(t.w * d.w));
    tt.x = __uint_as_float(f2tf32(t.x)); tt.y = __uint_as_float(f2tf32(t.y));
    tt.z = __uint_as_float(f2tf32(t.z)); tt.w = __uint_as_float(f2tf32(t.w));
    *(float4*)(g_Td + i4) = td;
    *(float4*)(g_Tt + i4) = tt;
}

// ---------------------------------------------------------------------------
// K2: g_X = H_v @ weight
// ---------------------------------------------------------------------------
__global__ void k_hvw(const float* __restrict__ Hv, const float* __restrict__ W) {
    int i = blockIdx.x, j = threadIdx.x;
    const float* hr = Hv + i * IN_V;
    float acc = 0.f;
#pragma unroll 16
    for (int k = 0; k < IN_V; k++) acc += hr[k] * W[k * OUT_V + j];
    g_X[i * OUT_V + j] = acc;
}

// ---------------------------------------------------------------------------
// K3: symmetric tf32 GEMM via mma.sync, upper-triangle tiles only.
//     2 CTAs/SM, one barrier per K-chunk, drained pipeline tail.
// ---------------------------------------------------------------------------
constexpr int BM = 128, BK = 16;
constexpr int LDA = 20;                    // floats; 80B rows keep 16B alignment
constexpr int STAGE_B = 2 * BM * LDA * 4;  // 20480 bytes (A half + B half)
constexpr int NSTG = 4;
constexpr int SMEM_G1 = NSTG * STAGE_B;    // 81920
constexpr int NT1 = NV / BM;               // 32
constexpr int NPAIR = NT1 * (NT1 + 1) / 2; // 528
constexpr int NK = NE / BK;                // 1024
constexpr int STR = 129;                   // epilogue staging stride

__global__ void __launch_bounds__(256, 2) k_gemm1(const float* __restrict__ adj) {
    extern __shared__ char smem[];
    const uint32_t sbase = s2u(smem);

    // triangular decode: pid -> (ti, tj), ti <= tj
    int ti = 0, rem = blockIdx.x;
    while (rem >= NT1 - ti) { rem -= NT1 - ti; ti++; }
    const int tj = ti + rem;
    const int bm = ti * BM, bn = tj * BM;

    const int tid  = threadIdx.x;
    const int lane = tid & 31;
    const int warp = tid >> 5;
    const int wm = warp & 3;
    const int wn = warp >> 2;
    const int fr = lane >> 2;
    const int fc = lane & 3;

    float acc[2][8][4];
#pragma unroll
    for (int i = 0; i < 2; i++)
#pragma unroll
        for (int j = 0; j < 8; j++)
#pragma unroll
            for (int k = 0; k < 4; k++) acc[i][j][k] = 0.f;

    // cp.async mapping: 256 threads; row = tid>>2 (0..63, +64), chunk = tid&3
    const int lrow = tid >> 2;
    const int lch  = tid & 3;
    const float* gA = g_Td + (size_t)(bm + lrow) * NE + lch * 4;
    const float* gB = g_Tt + (size_t)(bn + lrow) * NE + lch * 4;
    const uint32_t soA = (uint32_t)(lrow * LDA + lch * 4) * 4;
    const uint32_t soA2 = soA + (uint32_t)(64 * LDA) * 4;

    auto ISSUE = [&](int kc) {
        const int s = kc & (NSTG - 1);
        const uint32_t base = sbase + s * STAGE_B;
        const uint32_t baseB = base + BM * LDA * 4;
        const size_t k0 = (size_t)kc * BK;
        cp16(base + soA,  gA + k0);
        cp16(base + soA2, gA + (size_t)64 * NE + k0);
        cp16(baseB + soA,  gB + k0);
        cp16(baseB + soA2, gB + (size_t)64 * NE + k0);
        asm volatile("cp.async.commit_group;" ::: "memory");
    };

    auto COMPUTE = [&](int kc) {
        const int s = kc & (NSTG - 1);
        const float* As = (const float*)(smem + s * STAGE_B);
        const float* Bs = As + BM * LDA;
#pragma unroll
        for (int ks = 0; ks < BK; ks += 8) {
            uint32_t af[2][4];
#pragma unroll
            for (int mt = 0; mt < 2; mt++) {
                int rb = wm * 32 + mt * 16;
                af[mt][0] = __float_as_uint(As[(rb + fr) * LDA + ks + fc]);
                af[mt][1] = __float_as_uint(As[(rb + fr + 8) * LDA + ks + fc]);
                af[mt][2] = __float_as_uint(As[(rb + fr) * LDA + ks + fc + 4]);
                af[mt][3] = __float_as_uint(As[(rb + fr + 8) * LDA + ks + fc + 4]);
            }
            uint32_t bf[8][2];
#pragma unroll
            for (int nt = 0; nt < 8; nt++) {
                int cb = wn * 64 + nt * 8;
                bf[nt][0] = __float_as_uint(Bs[(cb + fr) * LDA + ks + fc]);
                bf[nt][1] = __float_as_uint(Bs[(cb + fr) * LDA + ks + fc + 4]);
            }
#pragma unroll
            for (int mt = 0; mt < 2; mt++)
#pragma unroll
                for (int nt = 0; nt < 8; nt++) {
                    asm volatile(
                        "mma.sync.aligned.m16n8k8.row.col.f32.tf32.tf32.f32 "
                        "{%0,%1,%2,%3}, {%4,%5,%6,%7}, {%8,%9}, {%0,%1,%2,%3};\n"
                        : "+f"(acc[mt][nt][0]), "+f"(acc[mt][nt][1]),
                          "+f"(acc[mt][nt][2]), "+f"(acc[mt][nt][3])
                        : "r"(af[mt][0]), "r"(af[mt][1]), "r"(af[mt][2]), "r"(af[mt][3]),
                          "r"(bf[nt][0]), "r"(bf[nt][1]));
                }
        }
    };

    ISSUE(0); ISSUE(1); ISSUE(2);
    // Mainloop: ONE barrier per iteration. The sync after wait_group orders
    // every thread past COMPUTE(kc-1) before ISSUE(kc+3) overwrites that stage.
    for (int kc = 0; kc < NK - 3; kc++) {
        asm volatile("cp.async.wait_group 2;" ::: "memory");
        __syncthreads();
        ISSUE(kc + 3);
        COMPUTE(kc);
    }
    // Drained tail: guarantee each stage's group completed before compute.
    asm volatile("cp.async.wait_group 1;" ::: "memory");
    __syncthreads();
    COMPUTE(NK - 3);
    asm volatile("cp.async.wait_group 0;" ::: "memory");
    __syncthreads();
    COMPUTE(NK - 2);
    COMPUTE(NK - 1);
    __syncthreads();

    // ---------------- epilogue: stage tile, write direct + transposed -------
    float* stg = (float*)smem;
#pragma unroll
    for (int mt = 0; mt < 2; mt++)
#pragma unroll
        for (int nt = 0; nt < 8; nt++) {
            int il0 = wm * 32 + mt * 16 + fr;
            int il1 = il0 + 8;
            int jl  = wn * 64 + nt * 8 + fc * 2;
            stg[il0 * STR + jl]     = acc[mt][nt][0];
            stg[il0 * STR + jl + 1] = acc[mt][nt][1];
            stg[il1 * STR + jl]     = acc[mt][nt][2];
            stg[il1 * STR + jl + 1] = acc[mt][nt][3];
        }
    __syncthreads();

    // direct block: A[bm+r][bn+c]
#pragma unroll 8
    for (int e = 0; e < 64; e++) {
        int idx = tid + e * 256;
        int r = idx >> 7, c = idx & 127;
        int gi = bm + r, gj = bn + c;
        float v = stg[r * STR + c];
        if (gi == gj) v = 1.f;
        g_A[(size_t)gi * NV + gj] = v * adj[(size_t)gi * NV + gj];
    }
    // transposed block: A[bn+r][bm+c]  (off-diagonal tiles only)
    if (ti != tj) {
#pragma unroll 8
        for (int e = 0; e < 64; e++) {
            int idx = tid + e * 256;
            int r = idx >> 7, c = idx & 127;
            int gi = bn + r, gj = bm + c;
            float v = stg[c * STR + r];
            g_A[(size_t)gi * NV + gj] = v * adj[(size_t)gi * NV + gj];
        }
    }
}

// ---------------------------------------------------------------------------
// K4a: ret = bias
// ---------------------------------------------------------------------------
__global__ void k_bias(float* __restrict__ ret, const float* __restrict__ bias) {
    int idx = blockIdx.x * blockDim.x + threadIdx.x;
    ret[idx] = bias[idx & (OUT_V - 1)];
}

// ---------------------------------------------------------------------------
// K4b: ret += g_A @ g_X   (split-K=4, atomics)
// ---------------------------------------------------------------------------
constexpr int BM2 = 32, KT2 = 32, NSPLIT = 4;

__global__ void __launch_bounds__(256) k_gemm2(float* __restrict__ ret) {
    __shared__ float As2[BM2][KT2 + 1];
    __shared__ float Xs[KT2][OUT_V];
    const int bm  = blockIdx.x * BM2;
    const int kc0 = blockIdx.y * (NV / NSPLIT);
    const int kc1 = kc0 + NV / NSPLIT;
    const int tid = threadIdx.x;
    const int tx = tid & 31;
    const int ty = tid >> 5;

    float acc[4][4];
#pragma unroll
    for (int i = 0; i < 4; i++)
#pragma unroll
        for (int j = 0; j < 4; j++) acc[i][j] = 0.f;

    for (int kt = kc0; kt < kc1; kt += KT2) {
        {
            int r = tid >> 3, c4 = (tid & 7) * 4;
            float4 v = *(const float4*)&g_A[(size_t)(bm + r) * NV + kt + c4];
            As2[r][c4] = v.x; As2[r][c4 + 1] = v.y;
            As2[r][c4 + 2] = v.z; As2[r][c4 + 3] = v.w;
        }
#pragma unroll
        for (int i = 0; i < 4; i++) {
            int f = tid + i * 256;
            int r = f >> 5, c4 = (f & 31) * 4;
            *(float4*)&Xs[r][c4] = *(const float4*)&g_X[(kt + r) * OUT_V + c4];
        }
        __syncthreads();
#pragma unroll 8
        for (int k = 0; k < KT2; k++) {
            float a0 = As2[ty * 4 + 0][k];
            float a1 = As2[ty * 4 + 1][k];
            float a2 = As2[ty * 4 + 2][k];
            float a3 = As2[ty * 4 + 3][k];
            float4 b = *(const float4*)&Xs[k][tx * 4];
            acc[0][0] += a0 * b.x; acc[0][1] += a0 * b.y; acc[0][2] += a0 * b.z; acc[0][3] += a0 * b.w;
            acc[1][0] += a1 * b.x; acc[1][1] += a1 * b.y; acc[1][2] += a1 * b.z; acc[1][3] += a1 * b.w;
            acc[2][0] += a2 * b.x; acc[2][1] += a2 * b.y; acc[2][2] += a2 * b.z; acc[2][3] += a2 * b.w;
            acc[3][0] += a3 * b.x; acc[3][1] += a3 * b.y; acc[3][2] += a3 * b.z; acc[3][3] += a3 * b.w;
        }
        __syncthreads();
    }
#pragma unroll
    for (int i = 0; i < 4; i++)
#pragma unroll
        for (int j = 0; j < 4; j++)
            atomicAdd(&ret[(bm + ty * 4 + i) * OUT_V + tx * 4 + j], acc[i][j]);
}

// ---------------------------------------------------------------------------
extern "C" void kernel_launch(void* const* d_in, const int* in_sizes, int n_in,
                              void* d_out, int out_size) {
    const float* Hv   = (const float*)d_in[0];
    const float* He   = (const float*)d_in[1];
    const float* adjv = (const float*)d_in[3];
    const float* T    = (const float*)d_in[4];
    const float* W    = (const float*)d_in[5];
    const float* p    = (const float*)d_in[6];
    const float* bias = (const float*)d_in[7];
    float* out = (float*)d_out;

    cudaFuncSetAttribute(k_gemm1, cudaFuncAttributeMaxDynamicSharedMemorySize, SMEM_G1);

    k_diag<<<NE / 256, 256>>>(He, p);
    k_prep<<<(int)(((size_t)NV * NE) / 1024), 256>>>(T);
    k_hvw<<<NV, OUT_V>>>(Hv, W);
    k_gemm1<<<NPAIR, 256, SMEM_G1>>>(adjv);
    k_bias<<<NV * OUT_V / 256, 256>>>(out, bias);
    k_gemm2<<<dim3(NV / BM2, NSPLIT), 256>>>(out);

    if (out_size >= NV * OUT_V + NE * IN_E) {
        cudaMemcpyAsync(out + NV * OUT_V, He,
                        (size_t)NE * IN_E * sizeof(float),
                        cudaMemcpyDeviceToDevice, 0);
    }
}

// round 7
// speedup vs baseline: 2.6590x; 1.2036x over previous
#include <cuda_runtime.h>
#include <cstdint>

#define NV 4096
#define NE 16384
#define IN_V 128
#define OUT_V 128
#define IN_E 64

// ---------------- device global scratch (no allocation allowed) -------------
// g_Td / g_Tt hold tf32-rounded operands with each 16-float K-chunk PERMUTED
// to order [c0,c4,c8,c12, c1,c5,c9,c13, c2,c6,c10,c14, c3,c7,c11,c15] so one
// LDS.128 yields a thread's mma fragment elements for both k8 steps.
__device__ float g_A[(size_t)NV * NV];            // adjusted adjacency, 64 MB
__device__ float g_Td[(size_t)NV * NE];           // rna_tf32(T * diag), permuted
__device__ float g_Tt[(size_t)NV * NE];           // rna_tf32(T), permuted
__device__ float g_diag[NE];
__device__ float g_X[NV * OUT_V];

__device__ __forceinline__ uint32_t f2tf32(float f) {
    uint32_t u; asm("cvt.rna.tf32.f32 %0, %1;" : "=r"(u) : "f"(f)); return u;
}
__device__ __forceinline__ uint32_t s2u(const void* p) {
    uint32_t a;
    asm("{ .reg .u64 t; cvta.to.shared.u64 t, %1; cvt.u32.u64 %0, t; }" : "=r"(a) : "l"(p));
    return a;
}
__device__ __forceinline__ void cp16(uint32_t dst, const void* src) {
    asm volatile("cp.async.cg.shared.global [%0], [%1], 16;" :: "r"(dst), "l"(src) : "memory");
}

// ---------------------------------------------------------------------------
// K1: g_diag[e] = dot(H_e[e,:], p)
// ---------------------------------------------------------------------------
__global__ void k_diag(const float* __restrict__ He, const float* __restrict__ p) {
    __shared__ float sp[IN_E];
    if (threadIdx.x < IN_E) sp[threadIdx.x] = p[threadIdx.x];
    __syncthreads();
    int e = blockIdx.x * blockDim.x + threadIdx.x;
    const float* row = He + (size_t)e * IN_E;
    float acc = 0.f;
#pragma unroll
    for (int k = 0; k < IN_E; k++) acc += row[k] * sp[k];
    g_diag[e] = acc;
}

// ---------------------------------------------------------------------------
// K1b: permuted-K tf32 operands.
// Output float4 at offset o4 (group g of chunk) = orig cols {b, b+4, b+8, b+12}
// where b = chunk*16 + g.
// ---------------------------------------------------------------------------
__global__ void __launch_bounds__(256) k_prep(const float* __restrict__ T) {
    size_t idx = (size_t)blockIdx.x * 256 + threadIdx.x;
    size_t o4 = idx * 4;
    int colin = (int)(o4 & (NE - 1));
    int g = (colin >> 2) & 3;
    size_t rowbase = o4 - colin;
    int b = (colin & ~15) + g;
    float t0 = T[rowbase + b];
    float t1 = T[rowbase + b + 4];
    float t2 = T[rowbase + b + 8];
    float t3 = T[rowbase + b + 12];
    float d0 = g_diag[b], d1 = g_diag[b + 4], d2 = g_diag[b + 8], d3 = g_diag[b + 12];
    float4 td, tt;
    td.x = __uint_as_float(f2tf32(t0 * d0)); td.y = __uint_as_float(f2tf32(t1 * d1));
    td.z = __uint_as_float(f2tf32(t2 * d2)); td.w = __uint_as_float(f2tf32(t3 * d3));
    tt.x = __uint_as_float(f2tf32(t0)); tt.y = __uint_as_float(f2tf32(t1));
    tt.z = __uint_as_float(f2tf32(t2)); tt.w = __uint_as_float(f2tf32(t3));
    *(float4*)(g_Td + o4) = td;
    *(float4*)(g_Tt + o4) = tt;
}

// ---------------------------------------------------------------------------
// K2: g_X = H_v @ weight
// ---------------------------------------------------------------------------
__global__ void k_hvw(const float* __restrict__ Hv, const float* __restrict__ W) {
    int i = blockIdx.x, j = threadIdx.x;
    const float* hr = Hv + i * IN_V;
    float acc = 0.f;
#pragma unroll 16
    for (int k = 0; k < IN_V; k++) acc += hr[k] * W[k * OUT_V + j];
    g_X[i * OUT_V + j] = acc;
}

// ---------------------------------------------------------------------------
// K3: symmetric tf32 GEMM, upper-triangle tiles. Permuted-K smem layout:
//     64B rows, XOR chunk swizzle -> conflict-free LDS.128 fragment loads.
// ---------------------------------------------------------------------------
constexpr int BM = 128, BK = 16;
constexpr int ROWB = 64;                     // bytes per smem row (16 floats)
constexpr int HALF_B = BM * ROWB;            // 8192
constexpr int STAGE_B = 2 * HALF_B;          // 16384 (A half + B half)
constexpr int NSTG = 4;
constexpr int SMEM_G1 = 66560;               // >= max(4*16384, 128*129*4 epilogue)
constexpr int NT1 = NV / BM;                 // 32
constexpr int NPAIR = NT1 * (NT1 + 1) / 2;   // 528
constexpr int NK = NE / BK;                  // 1024
constexpr int STR = 129;                     // epilogue staging stride

__global__ void __launch_bounds__(256, 2) k_gemm1(const float* __restrict__ adj) {
    extern __shared__ char smem[];
    const uint32_t sbase = s2u(smem);

    // triangular decode: pid -> (ti, tj), ti <= tj
    int ti = 0, rem = blockIdx.x;
    while (rem >= NT1 - ti) { rem -= NT1 - ti; ti++; }
    const int tj = ti + rem;
    const int bm = ti * BM, bn = tj * BM;

    const int tid  = threadIdx.x;
    const int lane = tid & 31;
    const int warp = tid >> 5;
    const int wm = warp & 3;
    const int wn = warp >> 2;
    const int fr = lane >> 2;
    const int fc = lane & 3;
    const int swoff = (fc ^ (fr & 3)) * 16;   // constant per-thread chunk swizzle

    float acc[2][8][4];
#pragma unroll
    for (int i = 0; i < 2; i++)
#pragma unroll
        for (int j = 0; j < 8; j++)
#pragma unroll
            for (int k = 0; k < 4; k++) acc[i][j][k] = 0.f;

    // cp.async mapping: 256 threads; row = tid>>2 (0..63, +64), chunk = tid&3
    const int lrow = tid >> 2;
    const int lch  = tid & 3;
    const float* gA = g_Td + (size_t)(bm + lrow) * NE + lch * 4;
    const float* gB = g_Tt + (size_t)(bn + lrow) * NE + lch * 4;
    const uint32_t soA  = (uint32_t)(lrow * ROWB + ((lch ^ (lrow & 3)) * 16));
    const uint32_t soA2 = soA + 64 * ROWB;

    auto ISSUE = [&](int kc) {
        const int s = kc & (NSTG - 1);
        const uint32_t base  = sbase + s * STAGE_B;
        const uint32_t baseB = base + HALF_B;
        const size_t k0 = (size_t)kc * BK;
        cp16(base + soA,   gA + k0);
        cp16(base + soA2,  gA + (size_t)64 * NE + k0);
        cp16(baseB + soA,  gB + k0);
        cp16(baseB + soA2, gB + (size_t)64 * NE + k0);
        asm volatile("cp.async.commit_group;" ::: "memory");
    };

    auto COMPUTE = [&](int kc) {
        const int s = kc & (NSTG - 1);
        const char* As = smem + s * STAGE_B;
        const char* Bs = As + HALF_B;
        // A fragments: 2 m-tiles x 2 rows, one LDS.128 each
        float4 a0[2], a1[2];
#pragma unroll
        for (int mt = 0; mt < 2; mt++) {
            int r0 = wm * 32 + mt * 16 + fr;
            a0[mt] = *(const float4*)(As + r0 * ROWB + swoff);
            a1[mt] = *(const float4*)(As + (r0 + 8) * ROWB + swoff);
        }
        // B fragments: 8 n-tiles, one LDS.128 each
        float4 bv[8];
#pragma unroll
        for (int nt = 0; nt < 8; nt++) {
            int r = wn * 64 + nt * 8 + fr;
            bv[nt] = *(const float4*)(Bs + r * ROWB + swoff);
        }
#pragma unroll
        for (int mt = 0; mt < 2; mt++) {
            uint32_t afk0[4] = { __float_as_uint(a0[mt].x), __float_as_uint(a1[mt].x),
                                 __float_as_uint(a0[mt].y), __float_as_uint(a1[mt].y) };
            uint32_t afk8[4] = { __float_as_uint(a0[mt].z), __float_as_uint(a1[mt].z),
                                 __float_as_uint(a0[mt].w), __float_as_uint(a1[mt].w) };
#pragma unroll
            for (int nt = 0; nt < 8; nt++) {
                asm volatile(
                    "mma.sync.aligned.m16n8k8.row.col.f32.tf32.tf32.f32 "
                    "{%0,%1,%2,%3}, {%4,%5,%6,%7}, {%8,%9}, {%0,%1,%2,%3};\n"
                    : "+f"(acc[mt][nt][0]), "+f"(acc[mt][nt][1]),
                      "+f"(acc[mt][nt][2]), "+f"(acc[mt][nt][3])
                    : "r"(afk0[0]), "r"(afk0[1]), "r"(afk0[2]), "r"(afk0[3]),
                      "r"(__float_as_uint(bv[nt].x)), "r"(__float_as_uint(bv[nt].y)));
                asm volatile(
                    "mma.sync.aligned.m16n8k8.row.col.f32.tf32.tf32.f32 "
                    "{%0,%1,%2,%3}, {%4,%5,%6,%7}, {%8,%9}, {%0,%1,%2,%3};\n"
                    : "+f"(acc[mt][nt][0]), "+f"(acc[mt][nt][1]),
                      "+f"(acc[mt][nt][2]), "+f"(acc[mt][nt][3])
                    : "r"(afk8[0]), "r"(afk8[1]), "r"(afk8[2]), "r"(afk8[3]),
                      "r"(__float_as_uint(bv[nt].z)), "r"(__float_as_uint(bv[nt].w)));
            }
        }
    };

    ISSUE(0); ISSUE(1); ISSUE(2);
    for (int kc = 0; kc < NK - 3; kc++) {
        asm volatile("cp.async.wait_group 2;" ::: "memory");
        __syncthreads();
        ISSUE(kc + 3);
        COMPUTE(kc);
    }
    asm volatile("cp.async.wait_group 1;" ::: "memory");
    __syncthreads();
    COMPUTE(NK - 3);
    asm volatile("cp.async.wait_group 0;" ::: "memory");
    __syncthreads();
    COMPUTE(NK - 2);
    COMPUTE(NK - 1);
    __syncthreads();

    // ---------------- epilogue: stage tile, write direct + transposed -------
    float* stg = (float*)smem;
#pragma unroll
    for (int mt = 0; mt < 2; mt++)
#pragma unroll
        for (int nt = 0; nt < 8; nt++) {
            int il0 = wm * 32 + mt * 16 + fr;
            int il1 = il0 + 8;
            int jl  = wn * 64 + nt * 8 + fc * 2;
            stg[il0 * STR + jl]     = acc[mt][nt][0];
            stg[il0 * STR + jl + 1] = acc[mt][nt][1];
            stg[il1 * STR + jl]     = acc[mt][nt][2];
            stg[il1 * STR + jl + 1] = acc[mt][nt][3];
        }
    __syncthreads();

    // direct block: A[bm+r][bn+c]
#pragma unroll 8
    for (int e = 0; e < 64; e++) {
        int idx = tid + e * 256;
        int r = idx >> 7, c = idx & 127;
        int gi = bm + r, gj = bn + c;
        float v = stg[r * STR + c];
        if (gi == gj) v = 1.f;
        g_A[(size_t)gi * NV + gj] = v * adj[(size_t)gi * NV + gj];
    }
    // transposed block: A[bn+r][bm+c]  (off-diagonal tiles only)
    if (ti != tj) {
#pragma unroll 8
        for (int e = 0; e < 64; e++) {
            int idx = tid + e * 256;
            int r = idx >> 7, c = idx & 127;
            int gi = bn + r, gj = bm + c;
            float v = stg[c * STR + r];
            g_A[(size_t)gi * NV + gj] = v * adj[(size_t)gi * NV + gj];
        }
    }
}

// ---------------------------------------------------------------------------
// K4a: ret = bias
// ---------------------------------------------------------------------------
__global__ void k_bias(float* __restrict__ ret, const float* __restrict__ bias) {
    int idx = blockIdx.x * blockDim.x + threadIdx.x;
    ret[idx] = bias[idx & (OUT_V - 1)];
}

// ---------------------------------------------------------------------------
// K4b: ret += g_A @ g_X   (split-K=4, atomics)
// ---------------------------------------------------------------------------
constexpr int BM2 = 32, KT2 = 32, NSPLIT = 4;

__global__ void __launch_bounds__(256) k_gemm2(float* __restrict__ ret) {
    __shared__ float As2[BM2][KT2 + 1];
    __shared__ float Xs[KT2][OUT_V];
    const int bm  = blockIdx.x * BM2;
    const int kc0 = blockIdx.y * (NV / NSPLIT);
    const int kc1 = kc0 + NV / NSPLIT;
    const int tid = threadIdx.x;
    const int tx = tid & 31;
    const int ty = tid >> 5;

    float acc[4][4];
#pragma unroll
    for (int i = 0; i < 4; i++)
#pragma unroll
        for (int j = 0; j < 4; j++) acc[i][j] = 0.f;

    for (int kt = kc0; kt < kc1; kt += KT2) {
        {
            int r = tid >> 3, c4 = (tid & 7) * 4;
            float4 v = *(const float4*)&g_A[(size_t)(bm + r) * NV + kt + c4];
            As2[r][c4] = v.x; As2[r][c4 + 1] = v.y;
            As2[r][c4 + 2] = v.z; As2[r][c4 + 3] = v.w;
        }
#pragma unroll
        for (int i = 0; i < 4; i++) {
            int f = tid + i * 256;
            int r = f >> 5, c4 = (f & 31) * 4;
            *(float4*)&Xs[r][c4] = *(const float4*)&g_X[(kt + r) * OUT_V + c4];
        }
        __syncthreads();
#pragma unroll 8
        for (int k = 0; k < KT2; k++) {
            float a0 = As2[ty * 4 + 0][k];
            float a1 = As2[ty * 4 + 1][k];
            float a2 = As2[ty * 4 + 2][k];
            float a3 = As2[ty * 4 + 3][k];
            float4 b = *(const float4*)&Xs[k][tx * 4];
            acc[0][0] += a0 * b.x; acc[0][1] += a0 * b.y; acc[0][2] += a0 * b.z; acc[0][3] += a0 * b.w;
            acc[1][0] += a1 * b.x; acc[1][1] += a1 * b.y; acc[1][2] += a1 * b.z; acc[1][3] += a1 * b.w;
            acc[2][0] += a2 * b.x; acc[2][1] += a2 * b.y; acc[2][2] += a2 * b.z; acc[2][3] += a2 * b.w;
            acc[3][0] += a3 * b.x; acc[3][1] += a3 * b.y; acc[3][2] += a3 * b.z; acc[3][3] += a3 * b.w;
        }
        __syncthreads();
    }
#pragma unroll
    for (int i = 0; i < 4; i++)
#pragma unroll
        for (int j = 0; j < 4; j++)
            atomicAdd(&ret[(bm + ty * 4 + i) * OUT_V + tx * 4 + j], acc[i][j]);
}

// ---------------------------------------------------------------------------
extern "C" void kernel_launch(void* const* d_in, const int* in_sizes, int n_in,
                              void* d_out, int out_size) {
    const float* Hv   = (const float*)d_in[0];
    const float* He   = (const float*)d_in[1];
    const float* adjv = (const float*)d_in[3];
    const float* T    = (const float*)d_in[4];
    const float* W    = (const float*)d_in[5];
    const float* p    = (const float*)d_in[6];
    const float* bias = (const float*)d_in[7];
    float* out = (float*)d_out;

    cudaFuncSetAttribute(k_gemm1, cudaFuncAttributeMaxDynamicSharedMemorySize, SMEM_G1);

    k_diag<<<NE / 256, 256>>>(He, p);
    k_prep<<<(int)(((size_t)NV * NE) / 1024), 256>>>(T);
    k_hvw<<<NV, OUT_V>>>(Hv, W);
    k_gemm1<<<NPAIR, 256, SMEM_G1>>>(adjv);
    k_bias<<<NV * OUT_V / 256, 256>>>(out, bias);
    k_gemm2<<<dim3(NV / BM2, NSPLIT), 256>>>(out);

    if (out_size >= NV * OUT_V + NE * IN_E) {
        cudaMemcpyAsync(out + NV * OUT_V, He,
                        (size_t)NE * IN_E * sizeof(float),
                        cudaMemcpyDeviceToDevice, 0);
    }
}

// round 9
// speedup vs baseline: 2.6741x; 1.0057x over previous
#include <cuda_runtime.h>
#include <cstdint>

#define NV 4096
#define NE 16384
#define IN_V 128
#define OUT_V 128
#define IN_E 64

// ---------------- device global scratch (no allocation allowed) -------------
// g_Td / g_Tt hold tf32-rounded operands with each 16-float K-chunk PERMUTED
// to order [c0,c4,c8,c12, c1,c5,c9,c13, c2,c6,c10,c14, c3,c7,c11,c15] so one
// LDS.128 yields a thread's mma fragment elements for both k8 steps.
__device__ float g_A[(size_t)NV * NV];            // adjusted adjacency, 64 MB
__device__ float g_Td[(size_t)NV * NE];           // rna_tf32(T * diag), permuted
__device__ float g_Tt[(size_t)NV * NE];           // rna_tf32(T), permuted
__device__ float g_diag[NE];
__device__ float g_X[NV * OUT_V];

__device__ __forceinline__ uint32_t f2tf32(float f) {
    uint32_t u; asm("cvt.rna.tf32.f32 %0, %1;" : "=r"(u) : "f"(f)); return u;
}
__device__ __forceinline__ uint32_t s2u(const void* p) {
    uint32_t a;
    asm("{ .reg .u64 t; cvta.to.shared.u64 t, %1; cvt.u32.u64 %0, t; }" : "=r"(a) : "l"(p));
    return a;
}
__device__ __forceinline__ void cp16(uint32_t dst, const void* src) {
    asm volatile("cp.async.cg.shared.global [%0], [%1], 16;" :: "r"(dst), "l"(src) : "memory");
}

// ---------------------------------------------------------------------------
// K1: g_diag[e] = dot(H_e[e,:], p)
// ---------------------------------------------------------------------------
__global__ void k_diag(const float* __restrict__ He, const float* __restrict__ p) {
    __shared__ float sp[IN_E];
    if (threadIdx.x < IN_E) sp[threadIdx.x] = p[threadIdx.x];
    __syncthreads();
    int e = blockIdx.x * blockDim.x + threadIdx.x;
    const float* row = He + (size_t)e * IN_E;
    float acc = 0.f;
#pragma unroll
    for (int k = 0; k < IN_E; k++) acc += row[k] * sp[k];
    g_diag[e] = acc;
}

// ---------------------------------------------------------------------------
// K1b: permuted-K tf32 operands.
// ---------------------------------------------------------------------------
__global__ void __launch_bounds__(256) k_prep(const float* __restrict__ T) {
    size_t idx = (size_t)blockIdx.x * 256 + threadIdx.x;
    size_t o4 = idx * 4;
    int colin = (int)(o4 & (NE - 1));
    int g = (colin >> 2) & 3;
    size_t rowbase = o4 - colin;
    int b = (colin & ~15) + g;
    float t0 = T[rowbase + b];
    float t1 = T[rowbase + b + 4];
    float t2 = T[rowbase + b + 8];
    float t3 = T[rowbase + b + 12];
    float d0 = g_diag[b], d1 = g_diag[b + 4], d2 = g_diag[b + 8], d3 = g_diag[b + 12];
    float4 td, tt;
    td.x = __uint_as_float(f2tf32(t0 * d0)); td.y = __uint_as_float(f2tf32(t1 * d1));
    td.z = __uint_as_float(f2tf32(t2 * d2)); td.w = __uint_as_float(f2tf32(t3 * d3));
    tt.x = __uint_as_float(f2tf32(t0)); tt.y = __uint_as_float(f2tf32(t1));
    tt.z = __uint_as_float(f2tf32(t2)); tt.w = __uint_as_float(f2tf32(t3));
    *(float4*)(g_Td + o4) = td;
    *(float4*)(g_Tt + o4) = tt;
}

// ---------------------------------------------------------------------------
// K2: g_X = H_v @ weight
// ---------------------------------------------------------------------------
__global__ void k_hvw(const float* __restrict__ Hv, const float* __restrict__ W) {
    int i = blockIdx.x, j = threadIdx.x;
    const float* hr = Hv + i * IN_V;
    float acc = 0.f;
#pragma unroll 16
    for (int k = 0; k < IN_V; k++) acc += hr[k] * W[k * OUT_V + j];
    g_X[i * OUT_V + j] = acc;
}

// ---------------------------------------------------------------------------
// K3: symmetric tf32 GEMM, upper-triangle tiles. Mainloop unrolled by NSTG
//     so all stage addresses are compile-time constants (kills IMAD overhead).
// ---------------------------------------------------------------------------
constexpr int BM = 128, BK = 16;
constexpr int ROWB = 64;                     // bytes per smem row (16 floats)
constexpr int HALF_B = BM * ROWB;            // 8192
constexpr int STAGE_B = 2 * HALF_B;          // 16384 (A half + B half)
constexpr int NSTG = 4;
constexpr int SMEM_G1 = 66560;               // >= max(4*16384, 128*129*4 epilogue)
constexpr int NT1 = NV / BM;                 // 32
constexpr int NPAIR = NT1 * (NT1 + 1) / 2;   // 528
constexpr int NK = NE / BK;                  // 1024
constexpr int STR = 129;                     // epilogue staging stride

__global__ void __launch_bounds__(256, 2) k_gemm1(const float* __restrict__ adj) {
    extern __shared__ char smem[];
    const uint32_t sbase = s2u(smem);

    // triangular decode: pid -> (ti, tj), ti <= tj
    int ti = 0, rem = blockIdx.x;
    while (rem >= NT1 - ti) { rem -= NT1 - ti; ti++; }
    const int tj = ti + rem;
    const int bm = ti * BM, bn = tj * BM;

    const int tid  = threadIdx.x;
    const int lane = tid & 31;
    const int warp = tid >> 5;
    const int wm = warp & 3;
    const int wn = warp >> 2;
    const int fr = lane >> 2;
    const int fc = lane & 3;
    const int swoff = (fc ^ (fr & 3)) * 16;   // constant per-thread chunk swizzle

    float acc[2][8][4];
#pragma unroll
    for (int i = 0; i < 2; i++)
#pragma unroll
        for (int j = 0; j < 8; j++)
#pragma unroll
            for (int k = 0; k < 4; k++) acc[i][j][k] = 0.f;

    // cp.async mapping: 256 threads; row = tid>>2 (0..63, +64), chunk = tid&3
    const int lrow = tid >> 2;
    const int lch  = tid & 3;
    const float* gA = g_Td + (size_t)(bm + lrow) * NE + lch * 4;
    const float* gB = g_Tt + (size_t)(bn + lrow) * NE + lch * 4;
    const uint32_t soA  = (uint32_t)(lrow * ROWB + ((lch ^ (lrow & 3)) * 16));
    const uint32_t soA2 = soA + 64 * ROWB;

    auto ISSUE = [&](int s, int kc) {
        const uint32_t base  = sbase + s * STAGE_B;
        const uint32_t baseB = base + HALF_B;
        const size_t k0 = (size_t)kc * BK;
        cp16(base + soA,   gA + k0);
        cp16(base + soA2,  gA + (size_t)64 * NE + k0);
        cp16(baseB + soA,  gB + k0);
        cp16(baseB + soA2, gB + (size_t)64 * NE + k0);
        asm volatile("cp.async.commit_group;" ::: "memory");
    };

    auto COMPUTE = [&](int s) {
        const char* As = smem + s * STAGE_B;
        const char* Bs = As + HALF_B;
        float4 a0[2], a1[2];
#pragma unroll
        for (int mt = 0; mt < 2; mt++) {
            int r0 = wm * 32 + mt * 16 + fr;
            a0[mt] = *(const float4*)(As + r0 * ROWB + swoff);
            a1[mt] = *(const float4*)(As + (r0 + 8) * ROWB + swoff);
        }
        float4 bv[8];
#pragma unroll
        for (int nt = 0; nt < 8; nt++) {
            int r = wn * 64 + nt * 8 + fr;
            bv[nt] = *(const float4*)(Bs + r * ROWB + swoff);
        }
#pragma unroll
        for (int mt = 0; mt < 2; mt++) {
            uint32_t afk0[4] = { __float_as_uint(a0[mt].x), __float_as_uint(a1[mt].x),
                                 __float_as_uint(a0[mt].y), __float_as_uint(a1[mt].y) };
            uint32_t afk8[4] = { __float_as_uint(a0[mt].z), __float_as_uint(a1[mt].z),
                                 __float_as_uint(a0[mt].w), __float_as_uint(a1[mt].w) };
#pragma unroll
            for (int nt = 0; nt < 8; nt++) {
                asm volatile(
                    "mma.sync.aligned.m16n8k8.row.col.f32.tf32.tf32.f32 "
                    "{%0,%1,%2,%3}, {%4,%5,%6,%7}, {%8,%9}, {%0,%1,%2,%3};\n"
                    : "+f"(acc[mt][nt][0]), "+f"(acc[mt][nt][1]),
                      "+f"(acc[mt][nt][2]), "+f"(acc[mt][nt][3])
                    : "r"(afk0[0]), "r"(afk0[1]), "r"(afk0[2]), "r"(afk0[3]),
                      "r"(__float_as_uint(bv[nt].x)), "r"(__float_as_uint(bv[nt].y)));
                asm volatile(
                    "mma.sync.aligned.m16n8k8.row.col.f32.tf32.tf32.f32 "
                    "{%0,%1,%2,%3}, {%4,%5,%6,%7}, {%8,%9}, {%0,%1,%2,%3};\n"
                    : "+f"(acc[mt][nt][0]), "+f"(acc[mt][nt][1]),
                      "+f"(acc[mt][nt][2]), "+f"(acc[mt][nt][3])
                    : "r"(afk8[0]), "r"(afk8[1]), "r"(afk8[2]), "r"(afk8[3]),
                      "r"(__float_as_uint(bv[nt].z)), "r"(__float_as_uint(bv[nt].w)));
            }
        }
    };

    ISSUE(0, 0); ISSUE(1, 1); ISSUE(2, 2);
    // Steady loop: kc multiple of 4 -> stage indices are constants per u.
    for (int kc = 0; kc < NK - 4; kc += 4) {
#pragma unroll
        for (int u = 0; u < 4; u++) {
            asm volatile("cp.async.wait_group 2;" ::: "memory");
            __syncthreads();
            ISSUE((u + 3) & 3, kc + u + 3);
            COMPUTE(u);
        }
    }
    // Tail: kc = NK-4 .. NK-1 (NK ≡ 0 mod 4 -> stages 0..3)
    asm volatile("cp.async.wait_group 2;" ::: "memory");
    __syncthreads();
    ISSUE(3, NK - 1);
    COMPUTE(0);
    asm volatile("cp.async.wait_group 2;" ::: "memory");
    __syncthreads();
    COMPUTE(1);
    asm volatile("cp.async.wait_group 1;" ::: "memory");
    __syncthreads();
    COMPUTE(2);
    asm volatile("cp.async.wait_group 0;" ::: "memory");
    __syncthreads();
    COMPUTE(3);
    __syncthreads();

    // ---------------- epilogue: stage tile, write direct + transposed -------
    float* stg = (float*)smem;
#pragma unroll
    for (int mt = 0; mt < 2; mt++)
#pragma unroll
        for (int nt = 0; nt < 8; nt++) {
            int il0 = wm * 32 + mt * 16 + fr;
            int il1 = il0 + 8;
            int jl  = wn * 64 + nt * 8 + fc * 2;
            stg[il0 * STR + jl]     = acc[mt][nt][0];
            stg[il0 * STR + jl + 1] = acc[mt][nt][1];
            stg[il1 * STR + jl]     = acc[mt][nt][2];
            stg[il1 * STR + jl + 1] = acc[mt][nt][3];
        }
    __syncthreads();

    // direct block: A[bm+r][bn+c]
#pragma unroll 8
    for (int e = 0; e < 64; e++) {
        int idx = tid + e * 256;
        int r = idx >> 7, c = idx & 127;
        int gi = bm + r, gj = bn + c;
        float v = stg[r * STR + c];
        if (gi == gj) v = 1.f;
        g_A[(size_t)gi * NV + gj] = v * adj[(size_t)gi * NV + gj];
    }
    // transposed block: A[bn+r][bm+c]  (off-diagonal tiles only)
    if (ti != tj) {
#pragma unroll 8
        for (int e = 0; e < 64; e++) {
            int idx = tid + e * 256;
            int r = idx >> 7, c = idx & 127;
            int gi = bn + r, gj = bm + c;
            float v = stg[c * STR + r];
            g_A[(size_t)gi * NV + gj] = v * adj[(size_t)gi * NV + gj];
        }
    }
}

// ---------------------------------------------------------------------------
// K4a: ret = bias
// ---------------------------------------------------------------------------
__global__ void k_bias(float* __restrict__ ret, const float* __restrict__ bias) {
    int idx = blockIdx.x * blockDim.x + threadIdx.x;
    ret[idx] = bias[idx & (OUT_V - 1)];
}

// ---------------------------------------------------------------------------
// K4b: ret += g_A @ g_X   (split-K=4, atomics)
// ---------------------------------------------------------------------------
constexpr int BM2 = 32, KT2 = 32, NSPLIT = 4;

__global__ void __launch_bounds__(256) k_gemm2(float* __restrict__ ret) {
    __shared__ float As2[BM2][KT2 + 1];
    __shared__ float Xs[KT2][OUT_V];
    const int bm  = blockIdx.x * BM2;
    const int kc0 = blockIdx.y * (NV / NSPLIT);
    const int kc1 = kc0 + NV / NSPLIT;
    const int tid = threadIdx.x;
    const int tx = tid & 31;
    const int ty = tid >> 5;

    float acc[4][4];
#pragma unroll
    for (int i = 0; i < 4; i++)
#pragma unroll
        for (int j = 0; j < 4; j++) acc[i][j] = 0.f;

    for (int kt = kc0; kt < kc1; kt += KT2) {
        {
            int r = tid >> 3, c4 = (tid & 7) * 4;
            float4 v = *(const float4*)&g_A[(size_t)(bm + r) * NV + kt + c4];
            As2[r][c4] = v.x; As2[r][c4 + 1] = v.y;
            As2[r][c4 + 2] = v.z; As2[r][c4 + 3] = v.w;
        }
#pragma unroll
        for (int i = 0; i < 4; i++) {
            int f = tid + i * 256;
            int r = f >> 5, c4 = (f & 31) * 4;
            *(float4*)&Xs[r][c4] = *(const float4*)&g_X[(kt + r) * OUT_V + c4];
        }
        __syncthreads();
#pragma unroll 8
        for (int k = 0; k < KT2; k++) {
            float a0 = As2[ty * 4 + 0][k];
            float a1 = As2[ty * 4 + 1][k];
            float a2 = As2[ty * 4 + 2][k];
            float a3 = As2[ty * 4 + 3][k];
            float4 b = *(const float4*)&Xs[k][tx * 4];
            acc[0][0] += a0 * b.x; acc[0][1] += a0 * b.y; acc[0][2] += a0 * b.z; acc[0][3] += a0 * b.w;
            acc[1][0] += a1 * b.x; acc[1][1] += a1 * b.y; acc[1][2] += a1 * b.z; acc[1][3] += a1 * b.w;
            acc[2][0] += a2 * b.x; acc[2][1] += a2 * b.y; acc[2][2] += a2 * b.z; acc[2][3] += a2 * b.w;
            acc[3][0] += a3 * b.x; acc[3][1] += a3 * b.y; acc[3][2] += a3 * b.z; acc[3][3] += a3 * b.w;
        }
        __syncthreads();
    }
#pragma unroll
    for (int i = 0; i < 4; i++)
#pragma unroll
        for (int j = 0; j < 4; j++)
            atomicAdd(&ret[(bm + ty * 4 + i) * OUT_V + tx * 4 + j], acc[i][j]);
}

// ---------------------------------------------------------------------------
extern "C" void kernel_launch(void* const* d_in, const int* in_sizes, int n_in,
                              void* d_out, int out_size) {
    const float* Hv   = (const float*)d_in[0];
    const float* He   = (const float*)d_in[1];
    const float* adjv = (const float*)d_in[3];
    const float* T    = (const float*)d_in[4];
    const float* W    = (const float*)d_in[5];
    const float* p    = (const float*)d_in[6];
    const float* bias = (const float*)d_in[7];
    float* out = (float*)d_out;

    cudaFuncSetAttribute(k_gemm1, cudaFuncAttributeMaxDynamicSharedMemorySize, SMEM_G1);

    k_diag<<<NE / 256, 256>>>(He, p);
    k_prep<<<(int)(((size_t)NV * NE) / 1024), 256>>>(T);
    k_hvw<<<NV, OUT_V>>>(Hv, W);
    k_gemm1<<<NPAIR, 256, SMEM_G1>>>(adjv);
    k_bias<<<NV * OUT_V / 256, 256>>>(out, bias);
    k_gemm2<<<dim3(NV / BM2, NSPLIT), 256>>>(out);

    if (out_size >= NV * OUT_V + NE * IN_E) {
        cudaMemcpyAsync(out + NV * OUT_V, He,
                        (size_t)NE * IN_E * sizeof(float),
                        cudaMemcpyDeviceToDevice, 0);
    }
}